// round 14
// baseline (speedup 1.0000x reference)
#include <cuda_runtime.h>
#include <stdint.h>

#define R 512
#define K 81
#define IMW_M1 1332.0f
#define IMH_M1 799.0f
#define XCLIP 4.135166556742356f   // log(1000/16)
#define SCORE_THRESH 0.001f
#define POST_NMS_TOPN 300
#define MAX_PER_IMG 100
#define NT 1024

// scratch (no allocations allowed)
__device__ unsigned long long g_rmax[R];   // per-roi packed (score_bits<<32 | 255-class)

// ---------------------------------------------------------------------------
// box decode for (roi r, class c), matching reference arithmetic order
// ---------------------------------------------------------------------------
__device__ __forceinline__ float4 decode_box(const float* __restrict__ rois,
                                             const float* __restrict__ deltas,
                                             int r, int c) {
    float4 roi = ((const float4*)rois)[r];
    float4 d = *(const float4*)(deltas + r * (4 * K) + c * 4);   // 16B aligned

    float w = roi.z - roi.x + 1.0f;
    float h = roi.w - roi.y + 1.0f;
    float cx = roi.x + 0.5f * w;
    float cy = roi.y + 0.5f * h;

    float dx = d.x / 10.0f;
    float dy = d.y / 10.0f;
    float dw = fminf(d.z / 5.0f, XCLIP);
    float dh = fminf(d.w / 5.0f, XCLIP);

    float pcx = dx * w + cx;
    float pcy = dy * h + cy;
    float pw = expf(dw) * w;
    float ph = expf(dh) * h;

    float4 o;
    o.x = fminf(fmaxf(pcx - 0.5f * pw, 0.0f), IMW_M1);
    o.y = fminf(fmaxf(pcy - 0.5f * ph, 0.0f), IMH_M1);
    o.z = fminf(fmaxf(pcx + 0.5f * pw - 1.0f, 0.0f), IMW_M1);
    o.w = fminf(fmaxf(pcy + 0.5f * ph - 1.0f, 0.0f), IMH_M1);
    return o;
}

// ---------------------------------------------------------------------------
// Hybrid bitonic sort of 512 u64 keys (ascending), 1 elem/thread, tid in [0,512).
// PROVEN ONLY inside 1024-thread blocks (R8-R10). Used only in nms_kernel.
// ---------------------------------------------------------------------------
__device__ __forceinline__ unsigned long long hybrid_sort512(
    unsigned long long key, int tid,
    unsigned long long* __restrict__ bufA,
    unsigned long long* __restrict__ bufB)
{
    const int lane = tid & 31;
    #pragma unroll
    for (int k2 = 2; k2 <= 32; k2 <<= 1) {
        #pragma unroll
        for (int j = k2 >> 1; j > 0; j >>= 1) {
            bool up = ((tid & k2) == 0);
            bool amLow = ((lane & j) == 0);
            unsigned long long pk = __shfl_xor_sync(0xFFFFFFFFu, key, j);
            bool keepMin = (up == amLow);
            bool take = keepMin ? (pk < key) : (pk > key);
            if (take) key = pk;
        }
    }
    int par = 0;
    #pragma unroll
    for (int k2 = 64; k2 <= 512; k2 <<= 1) {
        bool up = ((tid & k2) == 0);
        #pragma unroll
        for (int j = k2 >> 1; j >= 32; j >>= 1) {
            unsigned long long* buf = par ? bufB : bufA;
            buf[tid] = key;
            asm volatile("bar.sync 1, 512;" ::: "memory");
            unsigned long long pk = buf[tid ^ j];
            bool amLow = ((tid & j) == 0);
            bool keepMin = (up == amLow);
            bool take = keepMin ? (pk < key) : (pk > key);
            if (take) key = pk;
            par ^= 1;
        }
        #pragma unroll
        for (int j = 16; j > 0; j >>= 1) {
            bool amLow = ((lane & j) == 0);
            unsigned long long pk = __shfl_xor_sync(0xFFFFFFFFu, key, j);
            bool keepMin = (up == amLow);
            bool take = keepMin ? (pk < key) : (pk > key);
            if (take) key = pk;
        }
    }
    return key;
}

// ---------------------------------------------------------------------------
// Main kernel: decode + per-class NMS (one block/class) + packed atomicMax.
// Byte-identical phases to the passing R10 kernel.
// ---------------------------------------------------------------------------
__global__ void __launch_bounds__(NT, 1)
nms_kernel(const float* __restrict__ rois,
           const float* __restrict__ deltas,
           const float* __restrict__ scores) {
    __shared__ uint32_t smask[R * 16];          // suppression bits; head = sort scratch
    __shared__ float4   sbox[R];                // sorted: (x1, y1, x2+1, y2+1)
    __shared__ float    sarea[R];
    __shared__ uint32_t skeep[16];
    __shared__ float    sTop;                   // class max score

    unsigned long long* scratch = (unsigned long long*)smask;   // 1024 u64 capacity

    const int c = blockIdx.x;
    const int tid = threadIdx.x;
    const int wid = tid >> 5;
    const int lane = tid & 31;

    unsigned long long key = 0;   // sorted element of rank tid (warps 0-15)
    int orig = 0;

    if (wid < 16) {
        // sort key: descending score, ascending original index (softmax scores > 0)
        float s = scores[tid * K + c];
        key = (((unsigned long long)(~__float_as_uint(s))) << 32) | (uint32_t)tid;
        key = hybrid_sort512(key, tid, scratch, scratch + 512);
        orig = (int)(key & 0xFFFFFFFFull);
        if (tid == 0) sTop = __uint_as_float(~(uint32_t)(key >> 32));
    } else {
        // concurrently: decode boxes (disjoint from sort scratch)
        int t = tid - 512;
        sbox[t] = decode_box(rois, deltas, t, c);
    }
    __syncthreads();

    // read permuted box BEFORE zeroing; zero smask with all 1024 threads
    float4 b4 = make_float4(0.f, 0.f, 0.f, 0.f);
    if (wid < 16) b4 = sbox[orig];
    {
        uint4 z = make_uint4(0, 0, 0, 0);
        uint4* p = (uint4*)smask;
        p[tid] = z; p[tid + NT] = z;
    }
    __syncthreads();
    if (wid < 16) {
        // area in reference expression order, then store pre-incremented coords
        sarea[tid] = (b4.z - b4.x + 1.0f) * (b4.w - b4.y + 1.0f);
        sbox[tid] = make_float4(b4.x, b4.y, b4.z + 1.0f, b4.w + 1.0f);
    }
    __syncthreads();

    // ---- mask build: tiles of 32 rows x 64 cols (2 col boxes per lane) ----
    // iou > 0.5  <=>  3*inter > ra+ca  <=>  fmaf(3, inter, -ca) > ra
    if (wid < 16) {
        int w = wid;
        int i0 = w << 5;
        int j0 = (w << 5) + lane;
        float4 cb0 = sbox[j0];
        float nca0 = -sarea[j0];
        bool hasW1 = ((w & 1) == 0);
        float4 cb1 = cb0; float nca1 = nca0;
        if (hasW1) { cb1 = sbox[j0 + 32]; nca1 = -sarea[j0 + 32]; }
        uint32_t* mp = smask + i0 * 16 + w;
        #pragma unroll 8
        for (int ii = 0; ii < 32; ii++) {
            int i = i0 + ii;
            float4 rb = sbox[i];
            float ra = sarea[i];
            float iw0 = fminf(cb0.z, rb.z) - fmaxf(cb0.x, rb.x);
            float ih0 = fminf(cb0.w, rb.w) - fmaxf(cb0.y, rb.y);
            float in0 = fmaxf(iw0, 0.0f) * fmaxf(ih0, 0.0f);
            bool sup0 = (fmaf(3.0f, in0, nca0) > ra) && (j0 > i);
            uint32_t w0 = __ballot_sync(0xFFFFFFFFu, sup0);
            float iw1 = fminf(cb1.z, rb.z) - fmaxf(cb1.x, rb.x);
            float ih1 = fminf(cb1.w, rb.w) - fmaxf(cb1.y, rb.y);
            float in1 = fmaxf(iw1, 0.0f) * fmaxf(ih1, 0.0f);
            bool sup1 = hasW1 && (fmaf(3.0f, in1, nca1) > ra);
            uint32_t w1 = __ballot_sync(0xFFFFFFFFu, sup1);
            if (lane == ii) { mp[0] = w0; if (hasW1) mp[1] = w1; }
            mp += 16;
        }
    }
    // Full 64-col tiles: (cc, rc) with rc < 2*cc, cc in 1..7 -> 56 tiles.
    {
        int nfull, tbase;
        if (wid >= 16)      { nfull = 2; tbase = (wid - 16) * 2; }
        else if (wid & 1)   { nfull = 2; tbase = 32 + (wid >> 1) * 2; }
        else                { nfull = 1; tbase = 48 + (wid >> 1); }

        for (int q = 0; q < nfull; q++) {
            int t = tbase + q;
            int cc = (int)((1.0f + sqrtf(1.0f + 4.0f * (float)t)) * 0.5f);
            while (t < cc * (cc - 1)) cc--;
            while (t >= cc * (cc + 1)) cc++;
            int rc = t - cc * (cc - 1);

            int j0 = (cc << 6) + lane;
            float4 cb0 = sbox[j0];
            float4 cb1 = sbox[j0 + 32];
            float nca0 = -sarea[j0];
            float nca1 = -sarea[j0 + 32];
            int i0 = rc << 5;
            uint32_t* mp = smask + i0 * 16 + (cc << 1);
            #pragma unroll 8
            for (int ii = 0; ii < 32; ii++) {
                float4 rb = sbox[i0 + ii];
                float ra = sarea[i0 + ii];
                float iw0 = fminf(cb0.z, rb.z) - fmaxf(cb0.x, rb.x);
                float ih0 = fminf(cb0.w, rb.w) - fmaxf(cb0.y, rb.y);
                float in0 = fmaxf(iw0, 0.0f) * fmaxf(ih0, 0.0f);
                bool sup0 = (fmaf(3.0f, in0, nca0) > ra);
                uint32_t w0 = __ballot_sync(0xFFFFFFFFu, sup0);
                float iw1 = fminf(cb1.z, rb.z) - fmaxf(cb1.x, rb.x);
                float ih1 = fminf(cb1.w, rb.w) - fmaxf(cb1.y, rb.y);
                float in1 = fmaxf(iw1, 0.0f) * fmaxf(ih1, 0.0f);
                bool sup1 = (fmaf(3.0f, in1, nca1) > ra);
                uint32_t w1 = __ballot_sync(0xFFFFFFFFu, sup1);
                if (lane == ii) { mp[0] = w0; mp[1] = w1; }
                mp += 16;
            }
        }
    }
    __syncthreads();

    // ---- greedy suppression: warp 0, lane-replicated current word ----
    if (wid == 0) {
        uint32_t remw = 0;              // lane l (&15) owns removed word l&15
        const int lw = lane & 15;
        int kept = 0;
        #pragma unroll 1
        for (int ow = 0; ow < 16; ow++) {
            uint32_t cur = __shfl_sync(0xFFFFFFFFu, remw, ow);
            uint32_t mo[32];
            #pragma unroll
            for (int b = 0; b < 32; b++) mo[b] = smask[(ow * 32 + b) * 16 + ow];
            uint32_t kcur = 0;
            #pragma unroll
            for (int b = 0; b < 32; b++) {
                uint32_t ml = smask[(ow * 32 + b) * 16 + lw];
                if (!((cur >> b) & 1u)) {
                    kept++;
                    cur  |= mo[b];
                    remw |= ml;
                    if (kept <= POST_NMS_TOPN) kcur |= (1u << b);
                }
            }
            if (lane == 0) skeep[ow] = kcur;
        }
    }
    __syncthreads();

    // ---- per-roi class-max via packed atomicMax ----
    if (wid < 16) {
        bool cvalid = (c != 0) && (sTop > SCORE_THRESH);
        bool kp = (skeep[tid >> 5] >> (tid & 31)) & 1u;
        if (kp && cvalid) {
            uint32_t bits = ~(uint32_t)(key >> 32);   // score float bits (>0)
            unsigned long long pkey =
                (((unsigned long long)bits) << 32) | (unsigned int)(255 - c);
            atomicMax(&g_rmax[orig], pkey);
        }
    }
}

// ---------------------------------------------------------------------------
// Tail kernel: top-100 assembly (single block, 512 threads).
// Uses ONLY R3-proven mechanisms: plain global read + reset, shared-memory
// __syncthreads bitonic sort, direct writes.
// ---------------------------------------------------------------------------
__global__ void __launch_bounds__(512, 1)
tail_kernel(const float* __restrict__ rois,
            const float* __restrict__ deltas,
            float* __restrict__ out, int out_size) {
    __shared__ unsigned long long skeys[R];
    __shared__ int slabel[R];
    const int tid = threadIdx.x;

    // zero full output (poisoned by harness)
    for (int i = tid; i < out_size; i += 512) out[i] = 0.0f;

    // plain read + reset (element tid touched only by thread tid; replay-safe)
    unsigned long long v = g_rmax[tid];
    g_rmax[tid] = 0ull;
    uint32_t bits = (uint32_t)(v >> 32);            // 0 if nothing kept
    int lbl = (v != 0ull) ? (255 - (int)(v & 0xFFull)) : 0;
    slabel[tid] = lbl;
    skeys[tid] = (((unsigned long long)(~bits)) << 32) | (uint32_t)tid;
    __syncthreads();

    // shared-memory bitonic sort (ascending: score desc, idx asc) — R3-proven
    for (int k2 = 2; k2 <= R; k2 <<= 1) {
        for (int j = k2 >> 1; j > 0; j >>= 1) {
            int ixj = tid ^ j;
            if (ixj > tid) {
                bool up = ((tid & k2) == 0);
                unsigned long long a = skeys[tid], b = skeys[ixj];
                if ((a > b) == up) { skeys[tid] = b; skeys[ixj] = a; }
            }
            __syncthreads();
        }
    }

    if (tid < MAX_PER_IMG) {
        unsigned long long kk = skeys[tid];
        int r = (int)(kk & 0xFFFFFFFFull);
        float sc = __uint_as_float(~(uint32_t)(kk >> 32));
        int lbl2 = slabel[r];
        bool valid = sc > SCORE_THRESH;
        float4 bb = decode_box(rois, deltas, r, lbl2);

        if (out_size >= 5 * MAX_PER_IMG) {
            out[tid * 5 + 0] = valid ? sc : 0.0f;
            out[tid * 5 + 1] = valid ? bb.x : 0.0f;
            out[tid * 5 + 2] = valid ? bb.y : 0.0f;
            out[tid * 5 + 3] = valid ? bb.z : 0.0f;
            out[tid * 5 + 4] = valid ? bb.w : 0.0f;
        }
        if (out_size >= 6 * MAX_PER_IMG) out[5 * MAX_PER_IMG + tid] = (float)lbl2;
        if (out_size >= 7 * MAX_PER_IMG) out[6 * MAX_PER_IMG + tid] = (float)r;
    }
}

// ---------------------------------------------------------------------------
extern "C" void kernel_launch(void* const* d_in, const int* in_sizes, int n_in,
                              void* d_out, int out_size) {
    const float* rois   = (const float*)d_in[0];
    const float* deltas = (const float*)d_in[1];
    const float* scores = (const float*)d_in[2];
    float* out = (float*)d_out;

    nms_kernel<<<K, NT>>>(rois, deltas, scores);
    tail_kernel<<<1, 512>>>(rois, deltas, out, out_size);
}